// round 2
// baseline (speedup 1.0000x reference)
#include <cuda_runtime.h>
#include <cstdint>

#define NN 100000
#define NE 1600000
#define NG 64
#define DH 128

// -------- scratch (device globals: allocation-free) --------
__device__ __align__(16) float g_xa[(size_t)NN * DH];    // x @ W1a_top + b1a
__device__ __align__(16) float g_h1[(size_t)NE * DH];    // edge hidden pre-BN (819MB)
__device__ __align__(16) float g_agg[(size_t)NN * DH];   // scatter-add accumulator
__device__ float g_cnt[NN];                              // in-degree counts
__device__ __align__(16) float g_z1[(size_t)NN * DH];    // node hidden pre-BN
__device__ __align__(16) float g_ug[NG * DH];            // u @ W2a_u + b2a
__device__ float g_s1[2 * DH];                           // bn1 sum / sumsq
__device__ float g_s2[2 * DH];                           // bn2 sum / sumsq
__device__ float g_bn1[2 * DH];                          // bn1 scale / shift
__device__ float g_bn2[2 * DH];                          // bn2 scale / shift

__device__ __forceinline__ float2 up2(unsigned long long v) {
    float2 r;
    asm("mov.b64 {%0, %1}, %2;" : "=f"(r.x), "=f"(r.y) : "l"(v));
    return r;
}

// Block GEMM inner loop: C[128 x NB-tile] += A[128 x K] * B[K x NB]
// A row-major in smem with row stride KP (padded), B row-major stride NB.
// Accumulators packed as f32x2 pairs -> fma.rn.f32x2 (2x fp32 FMA rate on sm_103a).
template <int RI, int K, int NB, int KP>
__device__ __forceinline__ void gemm_px2(const float* __restrict__ As,
                                         const float* __restrict__ Bs,
                                         int rowBase, int colBase,
                                         unsigned long long (&acc)[RI][4]) {
#pragma unroll 8
    for (int k = 0; k < K; ++k) {
        const float* bp = Bs + k * NB + colBase;
        ulonglong2 q0 = *reinterpret_cast<const ulonglong2*>(bp);
        ulonglong2 q1 = *reinterpret_cast<const ulonglong2*>(bp + 4);
        unsigned long long b2[4] = {q0.x, q0.y, q1.x, q1.y};
#pragma unroll
        for (int i = 0; i < RI; ++i) {
            float a = As[(rowBase + i) * KP + k];
            unsigned long long a2;
            asm("mov.b64 %0, {%1, %1};" : "=l"(a2) : "f"(a));
#pragma unroll
            for (int j = 0; j < 4; ++j)
                asm("fma.rn.f32x2 %0, %1, %2, %0;" : "+l"(acc[i][j]) : "l"(a2), "l"(b2[j]));
        }
    }
}

// -------- K0: zero accumulators --------
__global__ void k_zero() {
    int i = blockIdx.x * blockDim.x + threadIdx.x;
    int stride = gridDim.x * blockDim.x;
    for (size_t idx = i; idx < (size_t)NN * DH; idx += stride) g_agg[idx] = 0.f;
    for (int idx = i; idx < NN; idx += stride) g_cnt[idx] = 0.f;
    if (i < 2 * DH) { g_s1[i] = 0.f; g_s2[i] = 0.f; }
}

// -------- K1: xa = x @ W1a[0:64,:] + b1a  (per node) --------
__global__ void __launch_bounds__(256) k_xa(const float* __restrict__ x,
                                            const float* __restrict__ W1a,
                                            const float* __restrict__ b1a) {
    extern __shared__ float sm[];
    float* As = sm;               // [128][68]
    float* Bs = sm + 128 * 68;    // [64][128]
    const int tid = threadIdx.x;
    const int n0 = blockIdx.x * 128;
    for (int t = tid; t < 128 * 64; t += 256) {
        int r = t >> 6, k = t & 63;
        int n = n0 + r;
        As[r * 68 + k] = (n < NN) ? x[(size_t)n * 64 + k] : 0.f;
    }
    for (int t = tid; t < 64 * 128; t += 256) Bs[t] = W1a[t];
    __syncthreads();
    unsigned long long acc[8][4] = {};
    const int tx = tid & 15, ty = tid >> 4;
    gemm_px2<8, 64, 128, 68>(As, Bs, ty * 8, tx * 8, acc);
    float bb[8];
#pragma unroll
    for (int j = 0; j < 8; j++) bb[j] = __ldg(&b1a[tx * 8 + j]);
#pragma unroll
    for (int i = 0; i < 8; i++) {
        int n = n0 + ty * 8 + i;
        if (n >= NN) continue;
        float v[8];
#pragma unroll
        for (int j = 0; j < 4; j++) {
            float2 p = up2(acc[i][j]);
            v[2 * j] = p.x + bb[2 * j];
            v[2 * j + 1] = p.y + bb[2 * j + 1];
        }
        float* op = g_xa + (size_t)n * 128 + tx * 8;
        *(float4*)op = make_float4(v[0], v[1], v[2], v[3]);
        *(float4*)(op + 4) = make_float4(v[4], v[5], v[6], v[7]);
    }
}

// -------- K_ug: ug = u @ W2a[192:256,:] + b2a  (per graph) --------
__global__ void k_ug(const float* __restrict__ u, const float* __restrict__ W2a,
                     const float* __restrict__ b2a) {
    int g = blockIdx.x, j = threadIdx.x;
    float s = b2a[j];
#pragma unroll 8
    for (int k = 0; k < 64; k++) s += u[g * 64 + k] * W2a[(192 + k) * 128 + j];
    g_ug[g * 128 + j] = s;
}

// -------- K2: h1 = xa[row] + ea @ W1a[64:128,:];  accumulate bn1 stats --------
__global__ void __launch_bounds__(256) k_edge1(const float* __restrict__ ea,
                                               const int* __restrict__ ei,
                                               const float* __restrict__ W1a) {
    extern __shared__ float sm[];
    float* As = sm;                 // [128][68]
    float* Bs = sm + 128 * 68;      // [64][128]
    float* s_sum = Bs + 64 * 128;   // [128]
    float* s_ssq = s_sum + 128;     // [128]
    const int tid = threadIdx.x;
    const int e0 = blockIdx.x * 128;
    for (int t = tid; t < 128 * 64; t += 256) {
        As[(t >> 6) * 68 + (t & 63)] = ea[(size_t)e0 * 64 + t];
    }
    for (int t = tid; t < 64 * 128; t += 256) Bs[t] = W1a[64 * 128 + t];
    if (tid < 128) { s_sum[tid] = 0.f; s_ssq[tid] = 0.f; }
    __syncthreads();
    unsigned long long acc[8][4] = {};
    const int tx = tid & 15, ty = tid >> 4;
    gemm_px2<8, 64, 128, 68>(As, Bs, ty * 8, tx * 8, acc);
    float ls[8] = {}, lq[8] = {};
#pragma unroll
    for (int i = 0; i < 8; i++) {
        int e = e0 + ty * 8 + i;
        int r = ei[e];
        const float* xr = g_xa + (size_t)r * 128 + tx * 8;
        float4 x0 = *(const float4*)xr, x1 = *(const float4*)(xr + 4);
        float xv[8] = {x0.x, x0.y, x0.z, x0.w, x1.x, x1.y, x1.z, x1.w};
        float v[8];
#pragma unroll
        for (int j = 0; j < 4; j++) {
            float2 p = up2(acc[i][j]);
            v[2 * j] = p.x;
            v[2 * j + 1] = p.y;
        }
#pragma unroll
        for (int j = 0; j < 8; j++) {
            v[j] += xv[j];
            ls[j] += v[j];
            lq[j] += v[j] * v[j];
        }
        float* hp = g_h1 + (size_t)e * 128 + tx * 8;
        *(float4*)hp = make_float4(v[0], v[1], v[2], v[3]);
        *(float4*)(hp + 4) = make_float4(v[4], v[5], v[6], v[7]);
    }
#pragma unroll
    for (int j = 0; j < 8; j++) {
        atomicAdd(&s_sum[tx * 8 + j], ls[j]);
        atomicAdd(&s_ssq[tx * 8 + j], lq[j]);
    }
    __syncthreads();
    if (tid < 128) {
        atomicAdd(&g_s1[tid], s_sum[tid]);
        atomicAdd(&g_s1[128 + tid], s_ssq[tid]);
    }
}

// -------- finalize BN stats -> scale/shift --------
__global__ void k_bnfin(const float* __restrict__ gamma, const float* __restrict__ beta,
                        int which, float invn) {
    int j = threadIdx.x;
    const float* s = which ? g_s2 : g_s1;
    float* bn = which ? g_bn2 : g_bn1;
    float mean = s[j] * invn;
    float var = fmaxf(s[128 + j] * invn - mean * mean, 0.f);
    float sc = gamma[j] * rsqrtf(var + 1e-5f);
    bn[j] = sc;
    bn[128 + j] = beta[j] - mean * sc;
}

// -------- K4: h2 = relu(bn1(h1)) @ W1b + b1b; scatter-add to agg[col] --------
__global__ void __launch_bounds__(256) k_edge2(const int* __restrict__ ei,
                                               const float* __restrict__ W1b,
                                               const float* __restrict__ b1b) {
    extern __shared__ float sm[];
    float* As = sm;                  // [128][132]
    float* Bs = sm + 128 * 132;      // [128][128]
    float* s_sc = Bs + 128 * 128;    // [128]
    float* s_sh = s_sc + 128;        // [128]
    const int tid = threadIdx.x;
    const int e0 = blockIdx.x * 128;
    if (tid < 128) { s_sc[tid] = g_bn1[tid]; s_sh[tid] = g_bn1[128 + tid]; }
    __syncthreads();
    for (int t = tid; t < 128 * 128; t += 256) {
        int r = t >> 7, k = t & 127;
        float v = g_h1[(size_t)e0 * 128 + t];
        As[r * 132 + k] = fmaxf(v * s_sc[k] + s_sh[k], 0.f);
    }
    for (int t = tid; t < 128 * 128; t += 256) Bs[t] = W1b[t];
    __syncthreads();
    unsigned long long acc[8][4] = {};
    const int tx = tid & 15, ty = tid >> 4;
    gemm_px2<8, 128, 128, 132>(As, Bs, ty * 8, tx * 8, acc);
    float bb[8];
#pragma unroll
    for (int j = 0; j < 8; j++) bb[j] = __ldg(&b1b[tx * 8 + j]);
    const int* col = ei + NE;
#pragma unroll
    for (int i = 0; i < 8; i++) {
        int e = e0 + ty * 8 + i;
        int c = col[e];
        float v[8];
#pragma unroll
        for (int j = 0; j < 4; j++) {
            float2 p = up2(acc[i][j]);
            v[2 * j] = p.x + bb[2 * j];
            v[2 * j + 1] = p.y + bb[2 * j + 1];
        }
        float* ap = g_agg + (size_t)c * 128 + tx * 8;
        asm volatile("red.global.add.v4.f32 [%0], {%1,%2,%3,%4};"
                     :: "l"(ap), "f"(v[0]), "f"(v[1]), "f"(v[2]), "f"(v[3]) : "memory");
        asm volatile("red.global.add.v4.f32 [%0], {%1,%2,%3,%4};"
                     :: "l"(ap + 4), "f"(v[4]), "f"(v[5]), "f"(v[6]), "f"(v[7]) : "memory");
    }
    if (tid < 128) atomicAdd(&g_cnt[col[e0 + tid]], 1.0f);
}

// -------- K5: z1 = x@W2a_x + (agg/cnt)@W2a_agg + ug[batch]; bn2 stats --------
__global__ void __launch_bounds__(256) k_node1(const float* __restrict__ x,
                                               const int* __restrict__ batch,
                                               const float* __restrict__ W2a) {
    extern __shared__ float sm[];
    float* As = sm;                  // [128][132]
    float* Bs = sm + 128 * 132;      // [128][128]
    float* s_ri = Bs + 128 * 128;    // [128]
    float* s_sum = s_ri + 128;       // [128]
    float* s_ssq = s_sum + 128;      // [128]
    const int tid = threadIdx.x;
    const int n0 = blockIdx.x * 128;
    if (tid < 128) {
        int n = n0 + tid;
        float c = (n < NN) ? g_cnt[n] : 1.f;
        s_ri[tid] = 1.f / fmaxf(c, 1.f);
        s_sum[tid] = 0.f;
        s_ssq[tid] = 0.f;
    }
    __syncthreads();
    // phase A: x part (K=64)
    for (int t = tid; t < 128 * 64; t += 256) {
        int r = t >> 6, k = t & 63;
        int n = n0 + r;
        As[r * 132 + k] = (n < NN) ? x[(size_t)n * 64 + k] : 0.f;
    }
    for (int t = tid; t < 64 * 128; t += 256) Bs[t] = W2a[t];
    __syncthreads();
    unsigned long long acc[8][4] = {};
    const int tx = tid & 15, ty = tid >> 4;
    gemm_px2<8, 64, 128, 132>(As, Bs, ty * 8, tx * 8, acc);
    __syncthreads();
    // phase B: normalized agg part (K=128)
    for (int t = tid; t < 128 * 128; t += 256) {
        int r = t >> 7, k = t & 127;
        int n = n0 + r;
        As[r * 132 + k] = (n < NN) ? g_agg[(size_t)n * 128 + k] * s_ri[r] : 0.f;
    }
    for (int t = tid; t < 128 * 128; t += 256) Bs[t] = W2a[64 * 128 + t];
    __syncthreads();
    gemm_px2<8, 128, 128, 132>(As, Bs, ty * 8, tx * 8, acc);
    float ls[8] = {}, lq[8] = {};
#pragma unroll
    for (int i = 0; i < 8; i++) {
        int n = n0 + ty * 8 + i;
        if (n >= NN) continue;
        int b = batch[n];
        const float* ur = g_ug + b * 128 + tx * 8;
        float4 u0 = *(const float4*)ur, u1 = *(const float4*)(ur + 4);
        float uv[8] = {u0.x, u0.y, u0.z, u0.w, u1.x, u1.y, u1.z, u1.w};
        float v[8];
#pragma unroll
        for (int j = 0; j < 4; j++) {
            float2 p = up2(acc[i][j]);
            v[2 * j] = p.x;
            v[2 * j + 1] = p.y;
        }
#pragma unroll
        for (int j = 0; j < 8; j++) {
            v[j] += uv[j];
            ls[j] += v[j];
            lq[j] += v[j] * v[j];
        }
        float* zp = g_z1 + (size_t)n * 128 + tx * 8;
        *(float4*)zp = make_float4(v[0], v[1], v[2], v[3]);
        *(float4*)(zp + 4) = make_float4(v[4], v[5], v[6], v[7]);
    }
#pragma unroll
    for (int j = 0; j < 8; j++) {
        atomicAdd(&s_sum[tx * 8 + j], ls[j]);
        atomicAdd(&s_ssq[tx * 8 + j], lq[j]);
    }
    __syncthreads();
    if (tid < 128) {
        atomicAdd(&g_s2[tid], s_sum[tid]);
        atomicAdd(&g_s2[128 + tid], s_ssq[tid]);
    }
}

// -------- K7: out = relu(bn2(z1)) @ W2b + b2b --------
__global__ void __launch_bounds__(256) k_node2(const float* __restrict__ W2b,
                                               const float* __restrict__ b2b,
                                               float* __restrict__ out) {
    extern __shared__ float sm[];
    float* As = sm;                 // [128][132]
    float* Bs = sm + 128 * 132;     // [128][64]
    float* s_sc = Bs + 128 * 64;
    float* s_sh = s_sc + 128;
    const int tid = threadIdx.x;
    const int n0 = blockIdx.x * 128;
    if (tid < 128) { s_sc[tid] = g_bn2[tid]; s_sh[tid] = g_bn2[128 + tid]; }
    __syncthreads();
    for (int t = tid; t < 128 * 128; t += 256) {
        int r = t >> 7, k = t & 127;
        int n = n0 + r;
        float v = (n < NN) ? g_z1[(size_t)n * 128 + k] : 0.f;
        As[r * 132 + k] = fmaxf(v * s_sc[k] + s_sh[k], 0.f);
    }
    for (int t = tid; t < 128 * 64; t += 256) Bs[t] = W2b[t];
    __syncthreads();
    unsigned long long acc[4][4] = {};
    const int tx = tid & 7, ty = tid >> 3;  // 8 x 32 thread grid, 4x8 microtile
    gemm_px2<4, 128, 64, 132>(As, Bs, ty * 4, tx * 8, acc);
    float bb[8];
#pragma unroll
    for (int j = 0; j < 8; j++) bb[j] = __ldg(&b2b[tx * 8 + j]);
#pragma unroll
    for (int i = 0; i < 4; i++) {
        int n = n0 + ty * 4 + i;
        if (n >= NN) continue;
        float v[8];
#pragma unroll
        for (int j = 0; j < 4; j++) {
            float2 p = up2(acc[i][j]);
            v[2 * j] = p.x + bb[2 * j];
            v[2 * j + 1] = p.y + bb[2 * j + 1];
        }
        float* op = out + (size_t)n * 64 + tx * 8;
        *(float4*)op = make_float4(v[0], v[1], v[2], v[3]);
        *(float4*)(op + 4) = make_float4(v[4], v[5], v[6], v[7]);
    }
}

extern "C" void kernel_launch(void* const* d_in, const int* in_sizes, int n_in,
                              void* d_out, int out_size) {
    const float* x = (const float*)d_in[0];
    const int* ei = (const int*)d_in[1];       // edge_index: int32 (JAX default int)
    const float* ea = (const float*)d_in[2];
    const float* u = (const float*)d_in[3];
    const int* batch = (const int*)d_in[4];    // batch: int32
    const float* W1a = (const float*)d_in[5];
    const float* b1a = (const float*)d_in[6];
    const float* gamma1 = (const float*)d_in[7];
    const float* beta1 = (const float*)d_in[8];
    const float* W1b = (const float*)d_in[9];
    const float* b1b = (const float*)d_in[10];
    const float* W2a = (const float*)d_in[11];
    const float* b2a = (const float*)d_in[12];
    const float* gamma2 = (const float*)d_in[13];
    const float* beta2 = (const float*)d_in[14];
    const float* W2b = (const float*)d_in[15];
    const float* b2b = (const float*)d_in[16];
    float* out = (float*)d_out;

    const int SM_XA = (128 * 68 + 64 * 128) * 4;
    const int SM_E1 = SM_XA + 256 * 4;
    const int SM_E2 = (128 * 132 + 128 * 128 + 256) * 4;
    const int SM_N1 = (128 * 132 + 128 * 128 + 384) * 4;
    const int SM_N2 = (128 * 132 + 128 * 64 + 256) * 4;

    cudaFuncSetAttribute(k_xa, cudaFuncAttributeMaxDynamicSharedMemorySize, SM_XA);
    cudaFuncSetAttribute(k_edge1, cudaFuncAttributeMaxDynamicSharedMemorySize, SM_E1);
    cudaFuncSetAttribute(k_edge2, cudaFuncAttributeMaxDynamicSharedMemorySize, SM_E2);
    cudaFuncSetAttribute(k_node1, cudaFuncAttributeMaxDynamicSharedMemorySize, SM_N1);
    cudaFuncSetAttribute(k_node2, cudaFuncAttributeMaxDynamicSharedMemorySize, SM_N2);

    k_zero<<<4096, 512>>>();
    k_xa<<<(NN + 127) / 128, 256, SM_XA>>>(x, W1a, b1a);
    k_ug<<<NG, 128>>>(u, W2a, b2a);
    k_edge1<<<NE / 128, 256, SM_E1>>>(ea, ei, W1a);
    k_bnfin<<<1, 128>>>(gamma1, beta1, 0, 1.0f / (float)NE);
    k_edge2<<<NE / 128, 256, SM_E2>>>(ei, W1b, b1b);
    k_node1<<<(NN + 127) / 128, 256, SM_N1>>>(x, batch, W2a);
    k_bnfin<<<1, 128>>>(gamma2, beta2, 1, 1.0f / (float)NN);
    k_node2<<<(NN + 127) / 128, 256, SM_N2>>>(W2b, b2b, out);
}

// round 4
// speedup vs baseline: 1.4924x; 1.4924x over previous
#include <cuda_runtime.h>
#include <cuda_bf16.h>
#include <cstdint>

#define NN 100000
#define NE 1600000
#define NG 64
#define DH 128

#define KP1 72    // padded K stride (elements) for K=64 tiles
#define KP2 136   // padded K stride for K=128 tiles

// -------- scratch (device globals: allocation-free) --------
__device__ __align__(16) float g_xa[(size_t)NN * DH];
__device__ __align__(16) float g_h1[(size_t)NE * DH];
__device__ __align__(16) float g_agg[(size_t)NN * DH];
__device__ float g_cnt[NN];
__device__ __align__(16) float g_z1[(size_t)NN * DH];
__device__ __align__(16) float g_ug[NG * DH];
__device__ float g_s1[2 * DH];
__device__ float g_s2[2 * DH];
__device__ float g_bn1[2 * DH];
__device__ float g_bn2[2 * DH];
// transposed weight images, bf16 hi/lo:  B^T[n][k] with padded k stride
__device__ __align__(16) __nv_bfloat16 g_B1h[128 * KP1];
__device__ __align__(16) __nv_bfloat16 g_B1l[128 * KP1];
__device__ __align__(16) __nv_bfloat16 g_B2h[128 * KP2];
__device__ __align__(16) __nv_bfloat16 g_B2l[128 * KP2];

// ================= warp mma helpers (base sm_103 HMMA path) =================
__device__ __forceinline__ void mma_bf16(float (&d)[4], uint32_t a0, uint32_t a1,
                                         uint32_t a2, uint32_t a3, uint32_t b0, uint32_t b1) {
    asm volatile(
        "mma.sync.aligned.m16n8k16.row.col.f32.bf16.bf16.f32 "
        "{%0,%1,%2,%3}, {%4,%5,%6,%7}, {%8,%9}, {%0,%1,%2,%3};"
        : "+f"(d[0]), "+f"(d[1]), "+f"(d[2]), "+f"(d[3])
        : "r"(a0), "r"(a1), "r"(a2), "r"(a3), "r"(b0), "r"(b1));
}

// One bf16 GEMM chain: acc[4][4][4] += A[128 x 16*NK] * B^T[128 x 16*NK]
// A, B in smem, row-major, k-stride KP elements. Warp tile 64m x 32n.
template <int KP, int NK>
__device__ __forceinline__ void run_chain(const __nv_bfloat16* __restrict__ Asm,
                                          const __nv_bfloat16* __restrict__ Bsm,
                                          int wm, int wn, int lane,
                                          float (&acc)[4][4][4]) {
    const int r0 = lane >> 2, kq = (lane & 3) * 2;
#pragma unroll
    for (int kc = 0; kc < NK; kc++) {
        const int kb = kc * 16 + kq;
        uint32_t a[4][4];
#pragma unroll
        for (int mi = 0; mi < 4; mi++) {
            const __nv_bfloat16* ap = Asm + (size_t)(wm + mi * 16 + r0) * KP + kb;
            a[mi][0] = *(const uint32_t*)ap;
            a[mi][1] = *(const uint32_t*)(ap + 8 * KP);
            a[mi][2] = *(const uint32_t*)(ap + 8);
            a[mi][3] = *(const uint32_t*)(ap + 8 * KP + 8);
        }
#pragma unroll
        for (int nj = 0; nj < 4; nj++) {
            const __nv_bfloat16* bp = Bsm + (size_t)(wn + nj * 8 + r0) * KP + kb;
            uint32_t b0 = *(const uint32_t*)bp;
            uint32_t b1 = *(const uint32_t*)(bp + 8);
#pragma unroll
            for (int mi = 0; mi < 4; mi++)
                mma_bf16(acc[mi][nj], a[mi][0], a[mi][1], a[mi][2], a[mi][3], b0, b1);
        }
    }
}

// stage accumulators to smem C[128][132] fp32
__device__ __forceinline__ void stage_C(float* __restrict__ Cst, int wm, int wn, int lane,
                                        const float (&acc)[4][4][4]) {
    const int r0 = lane >> 2, c0 = (lane & 3) * 2;
#pragma unroll
    for (int mi = 0; mi < 4; mi++) {
#pragma unroll
        for (int nj = 0; nj < 4; nj++) {
            int row = wm + mi * 16 + r0;
            int col = wn + nj * 8 + c0;
            *(float2*)&Cst[row * 132 + col] = make_float2(acc[mi][nj][0], acc[mi][nj][1]);
            *(float2*)&Cst[(row + 8) * 132 + col] = make_float2(acc[mi][nj][2], acc[mi][nj][3]);
        }
    }
}

__device__ __forceinline__ float2 up2(unsigned long long v) {
    float2 r;
    asm("mov.b64 {%0, %1}, %2;" : "=f"(r.x), "=f"(r.y) : "l"(v));
    return r;
}
template <int RI, int K, int NB, int KPW>
__device__ __forceinline__ void gemm_px2(const float* __restrict__ As,
                                         const float* __restrict__ Bs,
                                         int rowBase, int colBase,
                                         unsigned long long (&acc)[RI][4]) {
#pragma unroll 8
    for (int k = 0; k < K; ++k) {
        const float* bp = Bs + k * NB + colBase;
        ulonglong2 q0 = *reinterpret_cast<const ulonglong2*>(bp);
        ulonglong2 q1 = *reinterpret_cast<const ulonglong2*>(bp + 4);
        unsigned long long b2[4] = {q0.x, q0.y, q1.x, q1.y};
#pragma unroll
        for (int i = 0; i < RI; ++i) {
            float a = As[(rowBase + i) * KPW + k];
            unsigned long long a2;
            asm("mov.b64 %0, {%1, %1};" : "=l"(a2) : "f"(a));
#pragma unroll
            for (int j = 0; j < 4; ++j)
                asm("fma.rn.f32x2 %0, %1, %2, %0;" : "+l"(acc[i][j]) : "l"(a2), "l"(b2[j]));
        }
    }
}

__global__ void k_zero() {
    int i = blockIdx.x * blockDim.x + threadIdx.x;
    int stride = gridDim.x * blockDim.x;
    for (size_t idx = i; idx < (size_t)NN * DH; idx += stride) g_agg[idx] = 0.f;
    for (int idx = i; idx < NN; idx += stride) g_cnt[idx] = 0.f;
    if (i < 2 * DH) { g_s1[i] = 0.f; g_s2[i] = 0.f; }
}

// weight prep: transpose + hi/lo bf16 split
__global__ void k_prep(const float* __restrict__ W1a, const float* __restrict__ W1b) {
    int t = blockIdx.x * blockDim.x + threadIdx.x;
    int stride = gridDim.x * blockDim.x;
    for (int idx = t; idx < 128 * 64; idx += stride) {
        int k = idx >> 7, n = idx & 127;
        float w = W1a[(64 + k) * 128 + n];
        __nv_bfloat16 hi = __float2bfloat16(w);
        __nv_bfloat16 lo = __float2bfloat16(w - __bfloat162float(hi));
        g_B1h[n * KP1 + k] = hi;
        g_B1l[n * KP1 + k] = lo;
    }
    for (int idx = t; idx < 128 * 128; idx += stride) {
        int k = idx >> 7, n = idx & 127;
        float w = W1b[k * 128 + n];
        __nv_bfloat16 hi = __float2bfloat16(w);
        __nv_bfloat16 lo = __float2bfloat16(w - __bfloat162float(hi));
        g_B2h[n * KP2 + k] = hi;
        g_B2l[n * KP2 + k] = lo;
    }
}

__global__ void __launch_bounds__(256) k_xa(const float* __restrict__ x,
                                            const float* __restrict__ W1a,
                                            const float* __restrict__ b1a) {
    extern __shared__ float sm[];
    float* As = sm;
    float* Bs = sm + 128 * 68;
    const int tid = threadIdx.x;
    const int n0 = blockIdx.x * 128;
    for (int t = tid; t < 128 * 64; t += 256) {
        int r = t >> 6, k = t & 63;
        int n = n0 + r;
        As[r * 68 + k] = (n < NN) ? x[(size_t)n * 64 + k] : 0.f;
    }
    for (int t = tid; t < 64 * 128; t += 256) Bs[t] = W1a[t];
    __syncthreads();
    unsigned long long acc[8][4] = {};
    const int tx = tid & 15, ty = tid >> 4;
    gemm_px2<8, 64, 128, 68>(As, Bs, ty * 8, tx * 8, acc);
    float bb[8];
#pragma unroll
    for (int j = 0; j < 8; j++) bb[j] = __ldg(&b1a[tx * 8 + j]);
#pragma unroll
    for (int i = 0; i < 8; i++) {
        int n = n0 + ty * 8 + i;
        if (n >= NN) continue;
        float v[8];
#pragma unroll
        for (int j = 0; j < 4; j++) {
            float2 p = up2(acc[i][j]);
            v[2 * j] = p.x + bb[2 * j];
            v[2 * j + 1] = p.y + bb[2 * j + 1];
        }
        float* op = g_xa + (size_t)n * 128 + tx * 8;
        *(float4*)op = make_float4(v[0], v[1], v[2], v[3]);
        *(float4*)(op + 4) = make_float4(v[4], v[5], v[6], v[7]);
    }
}

__global__ void k_ug(const float* __restrict__ u, const float* __restrict__ W2a,
                     const float* __restrict__ b2a) {
    int g = blockIdx.x, j = threadIdx.x;
    float s = b2a[j];
#pragma unroll 8
    for (int k = 0; k < 64; k++) s += u[g * 64 + k] * W2a[(192 + k) * 128 + j];
    g_ug[g * 128 + j] = s;
}

__global__ void k_bnfin(const float* __restrict__ gamma, const float* __restrict__ beta,
                        int which, float invn) {
    int j = threadIdx.x;
    const float* s = which ? g_s2 : g_s1;
    float* bn = which ? g_bn2 : g_bn1;
    float mean = s[j] * invn;
    float var = fmaxf(s[128 + j] * invn - mean * mean, 0.f);
    float sc = gamma[j] * rsqrtf(var + 1e-5f);
    bn[j] = sc;
    bn[128 + j] = beta[j] - mean * sc;
}

// ================= k_edge1_mma: h1 = xa[row] + ea @ W1a_bot  (bf16x3 HMMA) =================
// smem bytes: A_hi@0 (18432), A_lo@18432, B_hi@36864, B_lo@55296, s_fin@73728 (1024)
// C stage (67584) overlays [0, 67584) after the MMA chains.
__global__ void __launch_bounds__(256, 2) k_edge1_mma(const float* __restrict__ ea,
                                                      const int* __restrict__ ei) {
    extern __shared__ char smc[];
    __nv_bfloat16* A_hi = (__nv_bfloat16*)(smc);
    __nv_bfloat16* A_lo = (__nv_bfloat16*)(smc + 18432);
    __nv_bfloat16* B_hi = (__nv_bfloat16*)(smc + 36864);
    __nv_bfloat16* B_lo = (__nv_bfloat16*)(smc + 55296);
    float* s_fin = (float*)(smc + 73728);
    float* Cst = (float*)smc;
    const int tid = threadIdx.x;
    const int wid = tid >> 5, lane = tid & 31;
    const int e0 = blockIdx.x * 128;

    if (tid < 256) s_fin[tid] = 0.f;
    // A (ea tile) -> hi/lo bf16
    for (int p = tid; p < 128 * 32; p += 256) {
        int row = p >> 5, kp = (p & 31) * 2;
        float2 a = *(const float2*)&ea[(size_t)(e0 + row) * 64 + kp];
        __nv_bfloat16 h0 = __float2bfloat16(a.x), h1v = __float2bfloat16(a.y);
        __nv_bfloat16 l0 = __float2bfloat16(a.x - __bfloat162float(h0));
        __nv_bfloat16 l1 = __float2bfloat16(a.y - __bfloat162float(h1v));
        *(__nv_bfloat162*)&A_hi[row * KP1 + kp] = __nv_bfloat162(h0, h1v);
        *(__nv_bfloat162*)&A_lo[row * KP1 + kp] = __nv_bfloat162(l0, l1);
    }
    for (int i = tid; i < 128 * KP1 / 8; i += 256) {
        ((uint4*)B_hi)[i] = ((const uint4*)g_B1h)[i];
        ((uint4*)B_lo)[i] = ((const uint4*)g_B1l)[i];
    }
    __syncthreads();

    const int wm = (wid & 1) * 64, wn = (wid >> 1) * 32;
    float acc[4][4][4] = {};
    run_chain<KP1, 4>(A_hi, B_hi, wm, wn, lane, acc);
    run_chain<KP1, 4>(A_lo, B_hi, wm, wn, lane, acc);
    run_chain<KP1, 4>(A_hi, B_lo, wm, wn, lane, acc);
    __syncthreads();
    stage_C(Cst, wm, wn, lane, acc);
    __syncthreads();

    // epilogue (same structure as passing R2 SIMT kernel)
    const int tx = tid & 15, ty = tid >> 4;
    float ls[8] = {}, lq[8] = {};
#pragma unroll
    for (int i = 0; i < 8; i++) {
        int e = e0 + ty * 8 + i;
        int r = ei[e];
        const float* cr = &Cst[(ty * 8 + i) * 132 + tx * 8];
        float4 c0 = *(const float4*)cr, c1 = *(const float4*)(cr + 4);
        const float* xr = g_xa + (size_t)r * 128 + tx * 8;
        float4 x0 = *(const float4*)xr, x1 = *(const float4*)(xr + 4);
        float v[8] = {c0.x + x0.x, c0.y + x0.y, c0.z + x0.z, c0.w + x0.w,
                      c1.x + x1.x, c1.y + x1.y, c1.z + x1.z, c1.w + x1.w};
#pragma unroll
        for (int j = 0; j < 8; j++) {
            ls[j] += v[j];
            lq[j] += v[j] * v[j];
        }
        float* hp = g_h1 + (size_t)e * 128 + tx * 8;
        *(float4*)hp = make_float4(v[0], v[1], v[2], v[3]);
        *(float4*)(hp + 4) = make_float4(v[4], v[5], v[6], v[7]);
    }
#pragma unroll
    for (int j = 0; j < 8; j++) {
        atomicAdd(&s_fin[tx * 8 + j], ls[j]);
        atomicAdd(&s_fin[128 + tx * 8 + j], lq[j]);
    }
    __syncthreads();
    if (tid < 128) {
        atomicAdd(&g_s1[tid], s_fin[tid]);
        atomicAdd(&g_s1[128 + tid], s_fin[128 + tid]);
    }
}

// ================= k_edge2_mma: h2 = relu(bn1(h1)) @ W1b + b1b ; scatter =================
// smem: A_hi@0 (34816), A_lo@34816, B@69632 (34816; Bh then Bl), s_sc@104448, s_sh@104960
// C stage (67584) overlays [0, 67584) after chains.
__global__ void __launch_bounds__(256, 2) k_edge2_mma(const int* __restrict__ ei,
                                                      const float* __restrict__ b1b) {
    extern __shared__ char smc[];
    __nv_bfloat16* A_hi = (__nv_bfloat16*)(smc);
    __nv_bfloat16* A_lo = (__nv_bfloat16*)(smc + 34816);
    __nv_bfloat16* Bsm = (__nv_bfloat16*)(smc + 69632);
    float* s_sc = (float*)(smc + 104448);
    float* s_sh = (float*)(smc + 104960);
    float* Cst = (float*)smc;
    const int tid = threadIdx.x;
    const int wid = tid >> 5, lane = tid & 31;
    const int e0 = blockIdx.x * 128;

    if (tid < 128) { s_sc[tid] = g_bn1[tid]; s_sh[tid] = g_bn1[128 + tid]; }
    __syncthreads();

    // A = relu(bn(h1)) -> hi/lo in one pass over h1
    for (int p = tid; p < 128 * 64; p += 256) {
        int row = p >> 6, kp = (p & 63) * 2;
        float2 h = *(const float2*)&g_h1[(size_t)(e0 + row) * 128 + kp];
        float v0 = fmaxf(h.x * s_sc[kp] + s_sh[kp], 0.f);
        float v1 = fmaxf(h.y * s_sc[kp + 1] + s_sh[kp + 1], 0.f);
        __nv_bfloat16 h0 = __float2bfloat16(v0), h1v = __float2bfloat16(v1);
        __nv_bfloat16 l0 = __float2bfloat16(v0 - __bfloat162float(h0));
        __nv_bfloat16 l1 = __float2bfloat16(v1 - __bfloat162float(h1v));
        *(__nv_bfloat162*)&A_hi[row * KP2 + kp] = __nv_bfloat162(h0, h1v);
        *(__nv_bfloat162*)&A_lo[row * KP2 + kp] = __nv_bfloat162(l0, l1);
    }
    for (int i = tid; i < 128 * KP2 / 8; i += 256) ((uint4*)Bsm)[i] = ((const uint4*)g_B2h)[i];
    __syncthreads();

    const int wm = (wid & 1) * 64, wn = (wid >> 1) * 32;
    float acc[4][4][4] = {};
    run_chain<KP2, 8>(A_hi, Bsm, wm, wn, lane, acc);
    run_chain<KP2, 8>(A_lo, Bsm, wm, wn, lane, acc);
    __syncthreads();
    for (int i = tid; i < 128 * KP2 / 8; i += 256) ((uint4*)Bsm)[i] = ((const uint4*)g_B2l)[i];
    __syncthreads();
    run_chain<KP2, 8>(A_hi, Bsm, wm, wn, lane, acc);
    __syncthreads();
    stage_C(Cst, wm, wn, lane, acc);
    __syncthreads();

    // epilogue: bias + vector reduce-scatter to g_agg[col[e]]
    const int tx = tid & 15, ty = tid >> 4;
    float bb[8];
#pragma unroll
    for (int j = 0; j < 8; j++) bb[j] = __ldg(&b1b[tx * 8 + j]);
    const int* col = ei + NE;
#pragma unroll
    for (int i = 0; i < 8; i++) {
        int e = e0 + ty * 8 + i;
        int c = col[e];
        const float* cr = &Cst[(ty * 8 + i) * 132 + tx * 8];
        float4 c0 = *(const float4*)cr, c1 = *(const float4*)(cr + 4);
        float v0 = c0.x + bb[0], v1 = c0.y + bb[1], v2 = c0.z + bb[2], v3 = c0.w + bb[3];
        float v4 = c1.x + bb[4], v5 = c1.y + bb[5], v6 = c1.z + bb[6], v7 = c1.w + bb[7];
        float* ap = g_agg + (size_t)c * 128 + tx * 8;
        asm volatile("red.global.add.v4.f32 [%0], {%1,%2,%3,%4};"
                     :: "l"(ap), "f"(v0), "f"(v1), "f"(v2), "f"(v3) : "memory");
        asm volatile("red.global.add.v4.f32 [%0], {%1,%2,%3,%4};"
                     :: "l"(ap + 4), "f"(v4), "f"(v5), "f"(v6), "f"(v7) : "memory");
    }
    if (tid < 128) atomicAdd(&g_cnt[col[e0 + tid]], 1.0f);
}

// ================= node-side kernels (SIMT, unchanged from passing R2) =================
__global__ void __launch_bounds__(256) k_node1(const float* __restrict__ x,
                                               const int* __restrict__ batch,
                                               const float* __restrict__ W2a) {
    extern __shared__ float sm[];
    float* As = sm;
    float* Bs = sm + 128 * 132;
    float* s_ri = Bs + 128 * 128;
    float* s_sum = s_ri + 128;
    float* s_ssq = s_sum + 128;
    const int tid = threadIdx.x;
    const int n0 = blockIdx.x * 128;
    if (tid < 128) {
        int n = n0 + tid;
        float c = (n < NN) ? g_cnt[n] : 1.f;
        s_ri[tid] = 1.f / fmaxf(c, 1.f);
        s_sum[tid] = 0.f;
        s_ssq[tid] = 0.f;
    }
    __syncthreads();
    for (int t = tid; t < 128 * 64; t += 256) {
        int r = t >> 6, k = t & 63;
        int n = n0 + r;
        As[r * 132 + k] = (n < NN) ? x[(size_t)n * 64 + k] : 0.f;
    }
    for (int t = tid; t < 64 * 128; t += 256) Bs[t] = W2a[t];
    __syncthreads();
    unsigned long long acc[8][4] = {};
    const int tx = tid & 15, ty = tid >> 4;
    gemm_px2<8, 64, 128, 132>(As, Bs, ty * 8, tx * 8, acc);
    __syncthreads();
    for (int t = tid; t < 128 * 128; t += 256) {
        int r = t >> 7, k = t & 127;
        int n = n0 + r;
        As[r * 132 + k] = (n < NN) ? g_agg[(size_t)n * 128 + k] * s_ri[r] : 0.f;
    }
    for (int t = tid; t < 128 * 128; t += 256) Bs[t] = W2a[64 * 128 + t];
    __syncthreads();
    gemm_px2<8, 128, 128, 132>(As, Bs, ty * 8, tx * 8, acc);
    float ls[8] = {}, lq[8] = {};
#pragma unroll
    for (int i = 0; i < 8; i++) {
        int n = n0 + ty * 8 + i;
        if (n >= NN) continue;
        int b = batch[n];
        const float* ur = g_ug + b * 128 + tx * 8;
        float4 u0 = *(const float4*)ur, u1 = *(const float4*)(ur + 4);
        float uv[8] = {u0.x, u0.y, u0.z, u0.w, u1.x, u1.y, u1.z, u1.w};
        float v[8];
#pragma unroll
        for (int j = 0; j < 4; j++) {
            float2 p = up2(acc[i][j]);
            v[2 * j] = p.x;
            v[2 * j + 1] = p.y;
        }
#pragma unroll
        for (int j = 0; j < 8; j++) {
            v[j] += uv[j];
            ls[j] += v[j];
            lq[j] += v[j] * v[j];
        }
        float* zp = g_z1 + (size_t)n * 128 + tx * 8;
        *(float4*)zp = make_float4(v[0], v[1], v[2], v[3]);
        *(float4*)(zp + 4) = make_float4(v[4], v[5], v[6], v[7]);
    }
#pragma unroll
    for (int j = 0; j < 8; j++) {
        atomicAdd(&s_sum[tx * 8 + j], ls[j]);
        atomicAdd(&s_ssq[tx * 8 + j], lq[j]);
    }
    __syncthreads();
    if (tid < 128) {
        atomicAdd(&g_s2[tid], s_sum[tid]);
        atomicAdd(&g_s2[128 + tid], s_ssq[tid]);
    }
}

__global__ void __launch_bounds__(256) k_node2(const float* __restrict__ W2b,
                                               const float* __restrict__ b2b,
                                               float* __restrict__ out) {
    extern __shared__ float sm[];
    float* As = sm;
    float* Bs = sm + 128 * 132;
    float* s_sc = Bs + 128 * 64;
    float* s_sh = s_sc + 128;
    const int tid = threadIdx.x;
    const int n0 = blockIdx.x * 128;
    if (tid < 128) { s_sc[tid] = g_bn2[tid]; s_sh[tid] = g_bn2[128 + tid]; }
    __syncthreads();
    for (int t = tid; t < 128 * 128; t += 256) {
        int r = t >> 7, k = t & 127;
        int n = n0 + r;
        float v = (n < NN) ? g_z1[(size_t)n * 128 + k] : 0.f;
        As[r * 132 + k] = fmaxf(v * s_sc[k] + s_sh[k], 0.f);
    }
    for (int t = tid; t < 128 * 64; t += 256) Bs[t] = W2b[t];
    __syncthreads();
    unsigned long long acc[4][4] = {};
    const int tx = tid & 7, ty = tid >> 3;
    gemm_px2<4, 128, 64, 132>(As, Bs, ty * 4, tx * 8, acc);
    float bb[8];
#pragma unroll
    for (int j = 0; j < 8; j++) bb[j] = __ldg(&b2b[tx * 8 + j]);
#pragma unroll
    for (int i = 0; i < 4; i++) {
        int n = n0 + ty * 4 + i;
        if (n >= NN) continue;
        float v[8];
#pragma unroll
        for (int j = 0; j < 4; j++) {
            float2 p = up2(acc[i][j]);
            v[2 * j] = p.x + bb[2 * j];
            v[2 * j + 1] = p.y + bb[2 * j + 1];
        }
        float* op = out + (size_t)n * 64 + tx * 8;
        *(float4*)op = make_float4(v[0], v[1], v[2], v[3]);
        *(float4*)(op + 4) = make_float4(v[4], v[5], v[6], v[7]);
    }
}

extern "C" void kernel_launch(void* const* d_in, const int* in_sizes, int n_in,
                              void* d_out, int out_size) {
    const float* x = (const float*)d_in[0];
    const int* ei = (const int*)d_in[1];
    const float* ea = (const float*)d_in[2];
    const float* u = (const float*)d_in[3];
    const int* batch = (const int*)d_in[4];
    const float* W1a = (const float*)d_in[5];
    const float* b1a = (const float*)d_in[6];
    const float* gamma1 = (const float*)d_in[7];
    const float* beta1 = (const float*)d_in[8];
    const float* W1b = (const float*)d_in[9];
    const float* b1b = (const float*)d_in[10];
    const float* W2a = (const float*)d_in[11];
    const float* b2a = (const float*)d_in[12];
    const float* gamma2 = (const float*)d_in[13];
    const float* beta2 = (const float*)d_in[14];
    const float* W2b = (const float*)d_in[15];
    const float* b2b = (const float*)d_in[16];
    float* out = (float*)d_out;

    const int SM_XA = (128 * 68 + 64 * 128) * 4;
    const int SM_E1 = 74752;
    const int SM_E2 = 105472;
    const int SM_N1 = (128 * 132 + 128 * 128 + 384) * 4;
    const int SM_N2 = (128 * 132 + 128 * 64 + 256) * 4;

    cudaFuncSetAttribute(k_xa, cudaFuncAttributeMaxDynamicSharedMemorySize, SM_XA);
    cudaFuncSetAttribute(k_edge1_mma, cudaFuncAttributeMaxDynamicSharedMemorySize, SM_E1);
    cudaFuncSetAttribute(k_edge2_mma, cudaFuncAttributeMaxDynamicSharedMemorySize, SM_E2);
    cudaFuncSetAttribute(k_node1, cudaFuncAttributeMaxDynamicSharedMemorySize, SM_N1);
    cudaFuncSetAttribute(k_node2, cudaFuncAttributeMaxDynamicSharedMemorySize, SM_N2);

    k_zero<<<4096, 512>>>();
    k_prep<<<64, 256>>>(W1a, W1b);
    k_xa<<<(NN + 127) / 128, 256, SM_XA>>>(x, W1a, b1a);
    k_ug<<<NG, 128>>>(u, W2a, b2a);
    k_edge1_mma<<<NE / 128, 256, SM_E1>>>(ea, ei);
    k_bnfin<<<1, 128>>>(gamma1, beta1, 0, 1.0f / (float)NE);
    k_edge2_mma<<<NE / 128, 256, SM_E2>>>(ei, b1b);
    k_node1<<<(NN + 127) / 128, 256, SM_N1>>>(x, batch, W2a);
    k_bnfin<<<1, 128>>>(gamma2, beta2, 1, 1.0f / (float)NN);
    k_node2<<<(NN + 127) / 128, 256, SM_N2>>>(W2b, b2b, out);
}